// round 3
// baseline (speedup 1.0000x reference)
#include <cuda_runtime.h>
#include <cfloat>
#include <math.h>

#define FULL 0xffffffffu

constexpr int B = 4;
constexpr int N = 8192;
constexpr int M = 4096;
constexpr int F = 64;
constexpr int K = 16;
constexpr float MIN_SIGMA = 1e-4f;

constexpr int   G    = 16;
constexpr int   G3   = G * G * G;
constexpr float GLO  = -3.2f;
constexpr float GH   = 0.4f;
constexpr float GINVH = 2.5f;
constexpr float EPS  = 1e-4f;   // AABB padding: conservative prune under fp rounding

// Scratch (device globals: no allocations allowed)
__device__ float  g_featT[(size_t)B * N * F];   // (B, N, F) transposed features
__device__ float4 g_sorted[B * N];              // {x, y, z, bitcast(orig idx)} cell-sorted
__device__ int    g_count[B * G3];              // histogram, then scatter cursor
__device__ int    g_start[B * (G3 + 1)];        // exclusive cell offsets

// ---------------------------------------------------------------------------
__device__ __forceinline__ int cell_of(float x, float y, float z) {
    int ix = min(G - 1, max(0, (int)floorf((x - GLO) * GINVH)));
    int iy = min(G - 1, max(0, (int)floorf((y - GLO) * GINVH)));
    int iz = min(G - 1, max(0, (int)floorf((z - GLO) * GINVH)));
    return (iz * G + iy) * G + ix;
}

// ---------------------------------------------------------------------------
__global__ void zero_kernel() {
    int i = blockIdx.x * blockDim.x + threadIdx.x;
    if (i < B * G3) g_count[i] = 0;
}

__global__ void hist_kernel(const float* __restrict__ pc) {
    int t = blockIdx.x * blockDim.x + threadIdx.x;
    if (t >= B * N) return;
    const int b = t >> 13, n = t & (N - 1);
    const float* p = pc + (size_t)b * 3 * N;
    atomicAdd(&g_count[b * G3 + cell_of(p[n], p[N + n], p[2 * N + n])], 1);
}

// Per-batch exclusive scan of 4096 counts (one 1024-thread block per batch).
__global__ void scan_kernel() {
    __shared__ int wsum[32];
    const int b = blockIdx.x, tid = threadIdx.x;
    const int lane = tid & 31, wid = tid >> 5;
    const int base = b * G3, o = tid * 4;
    int v0 = g_count[base + o],     v1 = g_count[base + o + 1];
    int v2 = g_count[base + o + 2], v3 = g_count[base + o + 3];
    const int tsum = v0 + v1 + v2 + v3;
    int inc = tsum;
    #pragma unroll
    for (int off = 1; off < 32; off <<= 1) {
        int nb = __shfl_up_sync(FULL, inc, off);
        if (lane >= off) inc += nb;
    }
    if (lane == 31) wsum[wid] = inc;
    __syncthreads();
    if (wid == 0) {
        int si = wsum[lane];
        #pragma unroll
        for (int off = 1; off < 32; off <<= 1) {
            int nb = __shfl_up_sync(FULL, si, off);
            if (lane >= off) si += nb;
        }
        wsum[lane] = si;
    }
    __syncthreads();
    int excl = (wid ? wsum[wid - 1] : 0) + inc - tsum;
    const int sb = b * (G3 + 1);
    g_start[sb + o] = excl;     g_count[base + o] = excl;     excl += v0;
    g_start[sb + o + 1] = excl; g_count[base + o + 1] = excl; excl += v1;
    g_start[sb + o + 2] = excl; g_count[base + o + 2] = excl; excl += v2;
    g_start[sb + o + 3] = excl; g_count[base + o + 3] = excl; excl += v3;
    if (tid == 1023) g_start[sb + G3] = excl;   // == N
}

__global__ void scatter_kernel(const float* __restrict__ pc) {
    int t = blockIdx.x * blockDim.x + threadIdx.x;
    if (t >= B * N) return;
    const int b = t >> 13, n = t & (N - 1);
    const float* p = pc + (size_t)b * 3 * N;
    const float x = p[n], y = p[N + n], z = p[2 * N + n];
    const int pos = atomicAdd(&g_count[b * G3 + cell_of(x, y, z)], 1);
    g_sorted[b * N + pos] = make_float4(x, y, z, __int_as_float(n));
}

// ---------------------------------------------------------------------------
__global__ void transpose_feat_kernel(const float* __restrict__ feat) {
    __shared__ float tile[32][33];
    const int b  = blockIdx.z;
    const int n0 = blockIdx.x * 32;
    const int f0 = blockIdx.y * 32;
    const int tx = threadIdx.x, ty = threadIdx.y;
    #pragma unroll
    for (int i = ty; i < 32; i += 8)
        tile[i][tx] = feat[(size_t)b * F * N + (size_t)(f0 + i) * N + (n0 + tx)];
    __syncthreads();
    #pragma unroll
    for (int i = ty; i < 32; i += 8)
        g_featT[((size_t)b * N + (n0 + i)) * F + (f0 + tx)] = tile[tx][i];
}

// ---------------------------------------------------------------------------
// Warp-cooperative top-K insert: sorted ascending list in lanes 0..K-1,
// candidates from any lane. threshold = current K-th value (warp-uniform).
// ---------------------------------------------------------------------------
__device__ __forceinline__ void topk_insert(float s, int pidx, int lane,
                                            float& val, int& idx,
                                            float& threshold) {
    unsigned bal = __ballot_sync(FULL, s < threshold);
    while (bal) {
        const int src = __ffs(bal) - 1;
        bal &= bal - 1;
        const float cs = __shfl_sync(FULL, s, src);
        if (cs < threshold) {
            const int ci = __shfl_sync(FULL, pidx, src);
            const unsigned less = __ballot_sync(FULL, (lane < K) && (val <= cs));
            const int pos = __popc(less);
            const float ot = __shfl_up_sync(FULL, val, 1);
            const int   oi = __shfl_up_sync(FULL, idx, 1);
            if (lane < K) {
                if (lane == pos)     { val = cs; idx = ci; }
                else if (lane > pos) { val = ot; idx = oi; }
            }
            threshold = __shfl_sync(FULL, val, K - 1);
        }
    }
}

// ---------------------------------------------------------------------------
// Query kernel: one warp per query. Expanding Chebyshev rings over the grid,
// exact per-run AABB dmin^2 pruning, conservative ring stop.
// ---------------------------------------------------------------------------
__global__ void __launch_bounds__(1024, 1)
soft_projection_query(const float* __restrict__ qc,
                      const float* __restrict__ temp,
                      float* __restrict__ out) {
    extern __shared__ char smraw[];
    float4* spts = (float4*)smraw;                       // 128KB
    int* cst = (int*)(smraw + (size_t)N * sizeof(float4)); // 16.4KB

    const int b = blockIdx.y;
    for (int i = threadIdx.x; i < N; i += blockDim.x) spts[i] = g_sorted[b * N + i];
    for (int i = threadIdx.x; i < G3 + 1; i += blockDim.x)
        cst[i] = g_start[b * (G3 + 1) + i];
    __syncthreads();

    const float t = *temp;
    const float inv_sigma = 1.0f / fmaxf(t * t, MIN_SIGMA);

    const int lane = threadIdx.x & 31;
    const int warp = threadIdx.x >> 5;
    const int wg = blockIdx.x * 32 + warp;
    const int wstride = gridDim.x * 32;

    const float* qcb = qc + (size_t)b * 3 * M;
    float* out_pts  = out + (size_t)b * 3 * M;
    float* out_feat = out + (size_t)B * 3 * M + (size_t)b * F * M;
    const float* featb = g_featT + (size_t)b * N * F;

    for (int m = wg; m < M; m += wstride) {
        const float qx = qcb[m], qy = qcb[M + m], qz = qcb[2 * M + m];
        const int ix = min(G - 1, max(0, (int)floorf((qx - GLO) * GINVH)));
        const int iy = min(G - 1, max(0, (int)floorf((qy - GLO) * GINVH)));
        const int iz = min(G - 1, max(0, (int)floorf((qz - GLO) * GINVH)));

        float val = FLT_MAX;
        int   idx = 0;
        float th = FLT_MAX;
        bool  init = false;   // first chunk initializes the list via bitonic-32

        auto process_run = [&](int x0, int x1, int y, int z,
                               float dy2z2) {
            // x-extent of run AABB (edge cells extend to infinity; EPS pad)
            const float xlo = (x0 == 0)     ? -INFINITY : GLO + x0 * GH - EPS;
            const float xhi = (x1 == G - 1) ?  INFINITY : GLO + (x1 + 1) * GH + EPS;
            const float nx = fminf(fmaxf(qx, xlo), xhi);
            const float dx = qx - nx;
            const float dmin2 = fmaf(dx, dx, dy2z2);
            if (dmin2 >= th) return;
            const int c0 = (z * G + y) * G + x0;
            const int s = cst[c0];
            const int e = cst[c0 + (x1 - x0) + 1];
            for (int pb = s; pb < e; pb += 32) {
                const int p = pb + lane;
                float d2 = FLT_MAX;
                int pid = 0;
                if (p < e) {
                    const float4 pt = spts[p];
                    const float ax = pt.x - qx, ay = pt.y - qy, az = pt.z - qz;
                    d2 = fmaf(ax, ax, fmaf(ay, ay, az * az));
                    pid = p;
                }
                if (!init) {
                    // bitonic sort 32 (d2, pid) ascending across the warp
                    #pragma unroll
                    for (int k = 2; k <= 32; k <<= 1) {
                        #pragma unroll
                        for (int j = k >> 1; j > 0; j >>= 1) {
                            const float ov = __shfl_xor_sync(FULL, d2, j);
                            const int   op = __shfl_xor_sync(FULL, pid, j);
                            const bool keep_small = (((lane & j) == 0) == ((lane & k) == 0));
                            const bool swp = keep_small ? (ov < d2) : (ov > d2);
                            if (swp) { d2 = ov; pid = op; }
                        }
                    }
                    val = d2; idx = pid;
                    th = __shfl_sync(FULL, val, K - 1);
                    init = true;
                } else {
                    topk_insert(d2, pid, lane, val, idx, th);
                }
            }
        };

        for (int r = 0; r < G; r++) {
            const int zlo = max(iz - r, 0), zhi = min(iz + r, G - 1);
            for (int z = zlo; z <= zhi; z++) {
                const bool zf = (z == iz - r) || (z == iz + r);
                const float zl = (z == 0)     ? -INFINITY : GLO + z * GH - EPS;
                const float zh = (z == G - 1) ?  INFINITY : GLO + (z + 1) * GH + EPS;
                const float nz = fminf(fmaxf(qz, zl), zh);
                const float dz = qz - nz;
                const float dz2 = dz * dz;
                const int ylo = max(iy - r, 0), yhi = min(iy + r, G - 1);
                for (int y = ylo; y <= yhi; y++) {
                    const bool yf = (y == iy - r) || (y == iy + r);
                    const float yl = (y == 0)     ? -INFINITY : GLO + y * GH - EPS;
                    const float yh = (y == G - 1) ?  INFINITY : GLO + (y + 1) * GH + EPS;
                    const float ny = fminf(fmaxf(qy, yl), yh);
                    const float dy = qy - ny;
                    const float dy2z2 = fmaf(dy, dy, dz2);
                    if (dy2z2 >= th) continue;   // whole row pruned
                    if (zf || yf) {
                        process_run(max(ix - r, 0), min(ix + r, G - 1), y, z, dy2z2);
                    } else {
                        if (ix - r >= 0) process_run(ix - r, ix - r, y, z, dy2z2);
                        if (ix + r <  G) process_run(ix + r, ix + r, y, z, dy2z2);
                    }
                }
            }
            // rings > r have dmin >= r*GH (edge extension only points outward)
            const float rb = r * GH - EPS;
            if (rb > 0.0f && th <= rb * rb) break;
        }

        // --- softmax over sorted top-16 (lanes 0..15) ---
        const float s_min = __shfl_sync(FULL, val, 0);
        const float e = (lane < K) ? __expf(-(val - s_min) * inv_sigma) : 0.0f;
        float esum = e;
        #pragma unroll
        for (int o = 16; o; o >>= 1) esum += __shfl_xor_sync(FULL, esum, o);
        const float w = e / esum;

        // --- projected points ---
        const float4 gp = spts[idx];
        float wx = w * gp.x, wy = w * gp.y, wz = w * gp.z;
        #pragma unroll
        for (int o = 16; o; o >>= 1) {
            wx += __shfl_xor_sync(FULL, wx, o);
            wy += __shfl_xor_sync(FULL, wy, o);
            wz += __shfl_xor_sync(FULL, wz, o);
        }
        if (lane == 0) {
            out_pts[m]         = wx;
            out_pts[M + m]     = wy;
            out_pts[2 * M + m] = wz;
        }

        // --- propagated features: 2 channels per lane ---
        const int og = __float_as_int(gp.w);   // original point index
        float a0 = 0.f, a1 = 0.f;
        #pragma unroll
        for (int j = 0; j < K; j++) {
            const float wj = __shfl_sync(FULL, w, j);
            const int   gj = __shfl_sync(FULL, og, j);
            const float2 f2 = *reinterpret_cast<const float2*>(
                featb + (size_t)gj * F + lane * 2);
            a0 = fmaf(wj, f2.x, a0);
            a1 = fmaf(wj, f2.y, a1);
        }
        out_feat[(size_t)(2 * lane) * M + m]     = a0;
        out_feat[(size_t)(2 * lane + 1) * M + m] = a1;
    }
}

// ---------------------------------------------------------------------------
extern "C" void kernel_launch(void* const* d_in, const int* in_sizes, int n_in,
                              void* d_out, int out_size) {
    const float* pc   = (const float*)d_in[0];  // (B,3,N)
    const float* qc   = (const float*)d_in[1];  // (B,3,M)
    const float* pf   = (const float*)d_in[2];  // (B,F,N)
    const float* temp = (const float*)d_in[3];  // scalar
    float* out = (float*)d_out;                 // (B,3,M) ++ (B,F,M)
    (void)in_sizes; (void)n_in; (void)out_size;

    const int smem = N * (int)sizeof(float4) + (G3 + 1) * (int)sizeof(int);
    cudaFuncSetAttribute(soft_projection_query,
                         cudaFuncAttributeMaxDynamicSharedMemorySize, smem);

    zero_kernel<<<(B * G3 + 1023) / 1024, 1024>>>();
    hist_kernel<<<(B * N + 1023) / 1024, 1024>>>(pc);
    scan_kernel<<<B, 1024>>>();
    scatter_kernel<<<(B * N + 1023) / 1024, 1024>>>(pc);
    transpose_feat_kernel<<<dim3(N / 32, F / 32, B), dim3(32, 8)>>>(pf);
    soft_projection_query<<<dim3(37, B), 1024, smem>>>(qc, temp, out);
}